// round 16
// baseline (speedup 1.0000x reference)
#include <cuda_runtime.h>
#include <math.h>
#include <string.h>

#define Bq 2
#define Lq 5
#define Nq 10
#define Cq 64
#define Hq 128
#define Wq 256
#define HWq (Hq * Wq)          // 32768
#define NHWq (Nq * HWq)        // 327680
#define OUTQ (Bq * Cq * HWq)   // 4194304

#define MGX (Wq / 64)          // 4
#define MGY (Hq / 8)           // 16
#define MASK_BLOCKS (MGX * MGY * Nq)   // 640

#define FBX 128                // fuse blocks per batch
#define NITER 4                // chunks per block (64 px each)
#define FBLK (FBX * Bq)        // 256 total fuse blocks (co-resident: 2/SM x 148 SMs >= 256)

// ---------------- scratch (all slots fully overwritten per launch; replay-safe) ----------------
__device__ float        g_mask[NHWq];
__device__ float        g_sum_b[Bq * Cq][FBX];   // private per-block pool partials (plain stores)
__device__ float        g_max_b[Bq * Cq][FBX];
__device__ int          g_blkcnt[MASK_BLOCKS];
__device__ unsigned int g_arrive;                // monotonic across graph replays

// separable 5-tap Gaussian, sigma=1:  k2d = (1/2pi) * g1[dy] * g1[dx]
__constant__ float GX[5] = {0.13533528f, 0.60653066f, 1.0f, 0.60653066f, 0.13533528f};
__constant__ float GY[5] = {0.13533528f * 0.15915494f, 0.60653066f * 0.15915494f,
                            0.15915494f, 0.60653066f * 0.15915494f, 0.13533528f * 0.15915494f};

__device__ __forceinline__ float fsig(float x) { return 1.0f / (1.0f + __expf(-x)); }

// ---- packed f32x2 helpers ----
__device__ __forceinline__ float2 fma2(float2 a, float2 b, float2 c) {
    unsigned long long ua, ub, uc, ud;
    memcpy(&ua, &a, 8); memcpy(&ub, &b, 8); memcpy(&uc, &c, 8);
    asm("fma.rn.f32x2 %0, %1, %2, %3;" : "=l"(ud) : "l"(ua), "l"(ub), "l"(uc));
    float2 d; memcpy(&d, &ud, 8); return d;
}
__device__ __forceinline__ float2 mul2(float2 a, float2 b) {
    unsigned long long ua, ub, ud;
    memcpy(&ua, &a, 8); memcpy(&ub, &b, 8);
    asm("mul.rn.f32x2 %0, %1, %2;" : "=l"(ud) : "l"(ua), "l"(ub));
    float2 d; memcpy(&d, &ud, 8); return d;
}
__device__ __forceinline__ float2 add2(float2 a, float2 b) {
    unsigned long long ua, ub, ud;
    memcpy(&ua, &a, 8); memcpy(&ub, &b, 8);
    asm("add.rn.f32x2 %0, %1, %2;" : "=l"(ud) : "l"(ua), "l"(ub));
    float2 d; memcpy(&d, &ud, 8); return d;
}

// ---- dynamic smem layout (float2 units) ----
#define NF_F    (NITER * Cq * 32)   // 8192 f2 = 64 KB fused-output staging
#define NF_BUF  (8 * 8 * 32)        // 2048 f2
#define NF_DOT  (Lq * 32)           // 160 f2
#define SMEM_TOTAL ((NF_F + NF_BUF + 3 * NF_DOT) * 8 + (8 + 64 + 64 + 64) * 4 + 256 * 4)

// ============ kernel 1: conf + separable gaussian + mask ============
__global__ void __launch_bounds__(256) conf_mask_kernel(
        const float* __restrict__ psm,
        const float* __restrict__ inv_delay,
        const float* __restrict__ ewc_w,
        const float* __restrict__ ewc_b) {
    const int TX = 64, TY = 8;
    __shared__ float sc[TY + 4][TX + 4];
    __shared__ float ht[TY + 4][TX];
    __shared__ int s_cnt;

    int n  = blockIdx.z;
    int w0 = blockIdx.x * TX;
    int h0 = blockIdx.y * TY;
    int tid = threadIdx.x;
    int flat = (n * MGY + blockIdx.y) * MGX + blockIdx.x;

    if (tid == 0) s_cnt = 0;

    float enc = tanhf(inv_delay[n] * ewc_w[0] + ewc_b[0]) + 1.0f;
    const float* p0 = psm + (size_t)(n * 2 + 0) * HWq;
    const float* p1 = psm + (size_t)(n * 2 + 1) * HWq;

#pragma unroll
    for (int k = 0; k < 4; k++) {
        int i = tid + k * 256;
        if (i < (TY + 4) * (TX + 4)) {
            int sy = i / (TX + 4);
            int sx = i - sy * (TX + 4);
            int h = h0 + sy - 2, w = w0 + sx - 2;
            float v = 0.0f;                               // zero-pad = 'SAME'
            if (h >= 0 && h < Hq && w >= 0 && w < Wq) {
                int idx = h * Wq + w;
                // sigmoid monotone: max(sig(a),sig(b)) == sig(max(a,b)) — one MUFU instead of two
                v = fsig(fmaxf(p0[idx], p1[idx])) * enc;
            }
            sc[sy][sx] = v;
        }
    }
    __syncthreads();

#pragma unroll
    for (int k = 0; k < 3; k++) {
        int i = tid + k * 256;
        int sy = i >> 6, sx = i & 63;
        float a = 0.0f;
#pragma unroll
        for (int d = 0; d < 5; d++) a += GX[d] * sc[sy][sx + d];
        ht[sy][sx] = a;
    }
    __syncthreads();

    int cnt = 0;
#pragma unroll
    for (int k = 0; k < 2; k++) {
        int px = tid + k * 256;
        int ty = px >> 6, tx = px & 63;
        float acc = 0.0f;
#pragma unroll
        for (int d = 0; d < 5; d++) acc += GY[d] * ht[ty + d][tx];
        float m = (acc > 0.01f || n % Lq == 0) ? 1.0f : 0.0f;   // ego always communicates
        g_mask[(size_t)n * HWq + (h0 + ty) * Wq + (w0 + tx)] = m;
        unsigned bal = __ballot_sync(0xffffffffu, m > 0.5f);
        if ((tid & 31) == 0) cnt += __popc(bal);
    }
    if ((tid & 31) == 0) atomicAdd(&s_cnt, cnt);
    __syncthreads();
    if (tid == 0) g_blkcnt[flat] = s_cnt;
    __syncthreads();
    cudaTriggerProgrammaticLaunchCompletion();
}

// ============ kernel 2: attention + pools + grid barrier + gate + gated write ============
__global__ void __launch_bounds__(256, 2) fuse_kernel(
        const float* __restrict__ x,
        const float* __restrict__ inv_delay,
        const float* __restrict__ ew_w,
        const float* __restrict__ ew_b,
        const float* __restrict__ w1,
        const float* __restrict__ w2,
        float* __restrict__ out, int out_size) {
    extern __shared__ char smraw[];
    float2* s_f    = (float2*)smraw;          // [NITER][Cq][32]
    float2* s_buf  = s_f + NF_F;              // [8][8][32]
    float2* s_dot  = s_buf + NF_BUF;          // [Lq][32]
    float2* s_mk   = s_dot + NF_DOT;          // [Lq][32]
    float2* s_coef = s_mk + NF_DOT;           // [Lq][32]
    float*  s_enw  = (float*)(s_coef + NF_DOT);   // [8]
    float*  s_avg  = s_enw + 8;               // [64]
    float*  s_mxp  = s_avg + 64;              // [64]
    float*  s_gate = s_mxp + 64;              // [64]
    int*    s_red  = (int*)(s_gate + 64);     // [256]

    const int b    = blockIdx.y;
    const int bx   = blockIdx.x;              // 0..FBX-1
    const int tid  = threadIdx.x;
    const int lane = tid & 31;
    const int wid  = tid >> 5;

    if (tid < Lq)
        s_enw[tid] = tanhf(inv_delay[b * Lq + tid] * ew_w[0] + ew_b[0]) + 1.0f;

    // iter-0 x loads front-issued before the PDL dependency sync (x is an external input)
    const float2* xrow = (const float2*)(x + ((size_t)(b * Lq) * Cq + wid * 8) * HWq);
    float2 xv[8][Lq];
    {
        int pp = (bx * NITER) * 32 + lane;
#pragma unroll
        for (int c = 0; c < 8; c++)
#pragma unroll
            for (int l = 0; l < Lq; l++)
                xv[c][l] = xrow[((size_t)l * Cq + c) * (HWq / 2) + pp];
    }

    cudaGridDependencySynchronize();          // conf_mask complete: g_mask/g_blkcnt visible
    __syncthreads();                          // s_enw visible

    for (int k = 0; k < NITER; k++) {
        int pp = (bx * NITER + k) * 32;

        if (k > 0) {
#pragma unroll
            for (int c = 0; c < 8; c++)
#pragma unroll
                for (int l = 0; l < Lq; l++)
                    xv[c][l] = xrow[((size_t)l * Cq + c) * (HWq / 2) + pp + lane];
        }
        if (wid < Lq)
            s_mk[wid * 32 + lane] =
                ((const float2*)(g_mask + (size_t)(b * Lq + wid) * HWq))[pp + lane];

        // packed partial dots over this warp's 8 channels
        float2 pd[Lq];
#pragma unroll
        for (int l = 0; l < Lq; l++) pd[l] = make_float2(0.0f, 0.0f);
#pragma unroll
        for (int c = 0; c < 8; c++) {
            float2 e = xv[c][0];
#pragma unroll
            for (int l = 0; l < Lq; l++) pd[l] = fma2(e, xv[c][l], pd[l]);
        }
#pragma unroll
        for (int l = 0; l < Lq; l++) s_buf[(wid * 8 + l) * 32 + lane] = pd[l];
        __syncthreads();

        // dot fan-in by 160-thread subset
        if (tid < Lq * 32) {
            int l = tid >> 5, ln = tid & 31;
            float2 t = make_float2(0.0f, 0.0f);
#pragma unroll
            for (int w = 0; w < 8; w++) t = add2(t, s_buf[(w * 8 + l) * 32 + ln]);
            s_dot[l * 32 + ln] = t;
        }
        __syncthreads();

        // softmax ONCE per pixel-pair (warp 0), coefs to smem
        if (tid < 32) {
            float2 s[Lq];
#pragma unroll
            for (int l = 0; l < Lq; l++)
                s[l] = mul2(make_float2(s_enw[l], s_enw[l]), s_mk[l * 32 + tid]);
            float2 s0c = mul2(s[0], make_float2(0.125f, 0.125f));   // 1/sqrt(64)
            float ex[Lq], ey[Lq], esx = 0.0f, esy = 0.0f;
#pragma unroll
            for (int l = 0; l < Lq; l++) {
                float2 scv = mul2(mul2(s_dot[l * 32 + tid], s0c), s[l]);
                ex[l] = __expf(scv.x); esx += ex[l];
                ey[l] = __expf(scv.y); esy += ey[l];
            }
            float2 inv = make_float2(1.0f / esx, 1.0f / esy);
#pragma unroll
            for (int l = 0; l < Lq; l++)
                s_coef[l * 32 + tid] = mul2(mul2(make_float2(ex[l], ey[l]), inv), s[l]);
        }
        __syncthreads();

        // fused outputs -> smem staging
        float2 coef[Lq];
#pragma unroll
        for (int l = 0; l < Lq; l++) coef[l] = s_coef[l * 32 + lane];
#pragma unroll
        for (int c = 0; c < 8; c++) {
            float2 f = make_float2(0.0f, 0.0f);
#pragma unroll
            for (int l = 0; l < Lq; l++) f = fma2(coef[l], xv[c][l], f);
            s_f[((k * Cq) + wid * 8 + c) * 32 + lane] = f;
        }
        __syncthreads();                      // s_buf/s_mk/s_coef free for next iter
    }

    // pooling sweep over staged outputs: 4 threads per channel
    {
        int ch = tid >> 2, sub = tid & 3;     // ch 0..63
        float a = 0.0f, m = -INFINITY;
#pragma unroll
        for (int k = 0; k < NITER; k++)
#pragma unroll
            for (int j = 0; j < 8; j++) {
                float2 v = s_f[((k * Cq) + ch) * 32 + sub * 8 + j];
                a += v.x + v.y;
                m = fmaxf(m, fmaxf(v.x, v.y));
            }
        a += __shfl_xor_sync(0xffffffffu, a, 1);
        m = fmaxf(m, __shfl_xor_sync(0xffffffffu, m, 1));
        a += __shfl_xor_sync(0xffffffffu, a, 2);
        m = fmaxf(m, __shfl_xor_sync(0xffffffffu, m, 2));
        if (sub == 0) {
            g_sum_b[b * Cq + ch][bx] = a;     // private slot, plain store
            g_max_b[b * Cq + ch][bx] = m;
        }
        __threadfence();                      // make stores device-visible before arrive
    }
    __syncthreads();

    // ---- grid barrier (replay-safe monotonic counter) ----
    if (tid == 0) {
        unsigned v = atomicAdd(&g_arrive, 1u);
        unsigned target = (v & ~(unsigned)(FBLK - 1)) + FBLK;
        unsigned cur;
        do {
            asm volatile("ld.acquire.gpu.u32 %0, [%1];" : "=r"(cur) : "l"(&g_arrive));
        } while (cur < target);
    }
    __syncthreads();

    // ---- fold pools for own batch ----
    {
        int c = tid & 63, q = tid >> 6;       // 4 quarters x 32 slots
        float a = 0.0f, m = -INFINITY;
#pragma unroll 8
        for (int j = 0; j < FBX / 4; j++) {
            int idx = q * (FBX / 4) + j;
            a += __ldcg(&g_sum_b[b * Cq + c][idx]);
            m = fmaxf(m, __ldcg(&g_max_b[b * Cq + c][idx]));
        }
        float* sp = (float*)s_buf;            // reuse as [4][64] x2
        sp[q * 64 + c] = a;
        sp[256 + q * 64 + c] = m;
    }
    __syncthreads();
    if (tid < Cq) {
        float* sp = (float*)s_buf;
        float a = sp[tid] + sp[64 + tid] + sp[128 + tid] + sp[192 + tid];
        float m = fmaxf(fmaxf(sp[256 + tid], sp[320 + tid]),
                        fmaxf(sp[384 + tid], sp[448 + tid]));
        s_avg[tid] = a * (1.0f / HWq);
        s_mxp[tid] = m;
    }
    __syncthreads();
    if (tid < Cq) {
        float og = 0.0f;
#pragma unroll
        for (int j = 0; j < 4; j++) {
            float sa = 0.0f, sm = 0.0f;
            for (int cc = 0; cc < Cq; cc++) {
                float w = w1[j * Cq + cc];
                sa += s_avg[cc] * w;
                sm += s_mxp[cc] * w;
            }
            og += (fmaxf(sa, 0.0f) + fmaxf(sm, 0.0f)) * w2[tid * 4 + j];
        }
        s_gate[tid] = 1.0f / (1.0f + expf(-og));
    }
    __syncthreads();

    // ---- gated write (single gmem write of out) ----
    float2* orow = (float2*)(out + ((size_t)b * Cq + wid * 8) * HWq);
#pragma unroll
    for (int k = 0; k < NITER; k++) {
        int pp = (bx * NITER + k) * 32 + lane;
#pragma unroll
        for (int c = 0; c < 8; c++) {
            float g = s_gate[wid * 8 + c];
            float2 v = s_f[((k * Cq) + wid * 8 + c) * 32 + lane];
            v.x *= g; v.y *= g;
            orow[((size_t)c) * (HWq / 2) + pp] = v;
        }
    }

    // ---- comm_rate by block (0,0) ----
    if (b == 0 && bx == 0) {
        int t = 0;
        for (int i = tid; i < MASK_BLOCKS; i += 256) t += g_blkcnt[i];
        s_red[tid] = t;
        for (int st = 128; st > 0; st >>= 1) {
            __syncthreads();
            if (tid < st) s_red[tid] += s_red[tid + st];
        }
        if (tid == 0 && out_size > OUTQ)
            out[OUTQ] = (float)s_red[0] / (float)NHWq;
    }
}

// ---------------- launch ----------------
extern "C" void kernel_launch(void* const* d_in, const int* in_sizes, int n_in,
                              void* d_out, int out_size) {
    const float* x         = (const float*)d_in[0];
    const float* psm       = (const float*)d_in[1];
    const float* inv_delay = (const float*)d_in[2];
    const float* ew_w      = (const float*)d_in[3];
    const float* ew_b      = (const float*)d_in[4];
    const float* ewc_w     = (const float*)d_in[5];
    const float* ewc_b     = (const float*)d_in[6];
    const float* sta_w1    = (const float*)d_in[7];
    const float* sta_w2    = (const float*)d_in[8];
    float* out = (float*)d_out;

    dim3 gm(MGX, MGY, Nq);
    conf_mask_kernel<<<gm, 256>>>(psm, inv_delay, ewc_w, ewc_b);

    cudaFuncSetAttribute(fuse_kernel,
                         cudaFuncAttributeMaxDynamicSharedMemorySize, SMEM_TOTAL);

    cudaLaunchAttribute pdl[1];
    pdl[0].id = cudaLaunchAttributeProgrammaticStreamSerialization;
    pdl[0].val.programmaticStreamSerializationAllowed = 1;

    cudaLaunchConfig_t cfg = {};
    cfg.gridDim  = dim3(FBX, Bq);
    cfg.blockDim = dim3(256);
    cfg.dynamicSmemBytes = SMEM_TOTAL;
    cfg.attrs = pdl; cfg.numAttrs = 1;
    cudaLaunchKernelEx(&cfg, fuse_kernel, x, inv_delay, ew_w, ew_b,
                       sta_w1, sta_w2, out, out_size);
}

// round 17
// speedup vs baseline: 1.5288x; 1.5288x over previous
#include <cuda_runtime.h>
#include <math.h>
#include <string.h>

#define Bq 2
#define Lq 5
#define Nq 10
#define Cq 64
#define Hq 128
#define Wq 256
#define HWq (Hq * Wq)          // 32768
#define NHWq (Nq * HWq)        // 327680
#define OUTQ (Bq * Cq * HWq)   // 4194304

#define MGX (Wq / 64)          // 4
#define MGY (Hq / 8)           // 16
#define MASK_BLOCKS (MGX * MGY * Nq)   // 640

#define NSLOT 64               // pooling replication factor (decontends L2 atomics)

// ---------------- scratch (no allocations allowed) ----------------
__device__ float        g_mask[NHWq];
__device__ float        g_sum_r[NSLOT][Bq * Cq];
__device__ unsigned int g_max_r[NSLOT][Bq * Cq];   // monotonic-encoded float max
__device__ float        g_gate[Bq * Cq];
__device__ int          g_blkcnt[MASK_BLOCKS];

// separable 5-tap Gaussian, sigma=1:  k2d = (1/2pi) * g1[dy] * g1[dx]
__constant__ float GX[5] = {0.13533528f, 0.60653066f, 1.0f, 0.60653066f, 0.13533528f};
__constant__ float GY[5] = {0.13533528f * 0.15915494f, 0.60653066f * 0.15915494f,
                            0.15915494f, 0.60653066f * 0.15915494f, 0.13533528f * 0.15915494f};

__device__ __forceinline__ float fsig(float x) { return 1.0f / (1.0f + __expf(-x)); }

// monotonic float<->uint order-preserving encode (max identity = 0u)
__device__ __forceinline__ unsigned int fenc(float f) {
    unsigned int u = __float_as_uint(f);
    return (u & 0x80000000u) ? ~u : (u | 0x80000000u);
}
__device__ __forceinline__ float fdec(unsigned int e) {
    return __uint_as_float((e & 0x80000000u) ? (e & 0x7FFFFFFFu) : ~e);
}

// ---- packed f32x2 helpers (Blackwell; PTX-only, ptxas never auto-fuses) ----
__device__ __forceinline__ float2 fma2(float2 a, float2 b, float2 c) {
    unsigned long long ua, ub, uc, ud;
    memcpy(&ua, &a, 8); memcpy(&ub, &b, 8); memcpy(&uc, &c, 8);
    asm("fma.rn.f32x2 %0, %1, %2, %3;" : "=l"(ud) : "l"(ua), "l"(ub), "l"(uc));
    float2 d; memcpy(&d, &ud, 8); return d;
}
__device__ __forceinline__ float2 mul2(float2 a, float2 b) {
    unsigned long long ua, ub, ud;
    memcpy(&ua, &a, 8); memcpy(&ub, &b, 8);
    asm("mul.rn.f32x2 %0, %1, %2;" : "=l"(ud) : "l"(ua), "l"(ub));
    float2 d; memcpy(&d, &ud, 8); return d;
}
__device__ __forceinline__ float2 add2(float2 a, float2 b) {
    unsigned long long ua, ub, ud;
    memcpy(&ua, &a, 8); memcpy(&ub, &b, 8);
    asm("add.rn.f32x2 %0, %1, %2;" : "=l"(ud) : "l"(ua), "l"(ub));
    float2 d; memcpy(&d, &ud, 8); return d;
}

// ============ kernel 1: conf + separable gaussian + mask (2 px/thread, 64x8 tiles) ============
__global__ void __launch_bounds__(256) conf_mask_kernel(
        const float* __restrict__ psm,
        const float* __restrict__ inv_delay,
        const float* __restrict__ ewc_w,
        const float* __restrict__ ewc_b) {
    const int TX = 64, TY = 8;
    __shared__ float sc[TY + 4][TX + 4];
    __shared__ float ht[TY + 4][TX];
    __shared__ int s_cnt;

    int n  = blockIdx.z;
    int w0 = blockIdx.x * TX;
    int h0 = blockIdx.y * TY;
    int tid = threadIdx.x;
    int flat = (n * MGY + blockIdx.y) * MGX + blockIdx.x;

    if (flat < NSLOT) {
        if (tid < Bq * Cq)            g_sum_r[flat][tid] = 0.0f;
        else if (tid < 2 * Bq * Cq)   g_max_r[flat][tid - Bq * Cq] = 0u;
    }
    if (tid == 0) s_cnt = 0;

    float enc = tanhf(inv_delay[n] * ewc_w[0] + ewc_b[0]) + 1.0f;
    const float* p0 = psm + (size_t)(n * 2 + 0) * HWq;
    const float* p1 = psm + (size_t)(n * 2 + 1) * HWq;

#pragma unroll
    for (int k = 0; k < 4; k++) {
        int i = tid + k * 256;
        if (i < (TY + 4) * (TX + 4)) {
            int sy = i / (TX + 4);
            int sx = i - sy * (TX + 4);
            int h = h0 + sy - 2, w = w0 + sx - 2;
            float v = 0.0f;                               // zero-pad = 'SAME'
            if (h >= 0 && h < Hq && w >= 0 && w < Wq) {
                int idx = h * Wq + w;
                // sigmoid monotone: max(sig(a),sig(b)) == sig(max(a,b)) — one MUFU not two
                v = fsig(fmaxf(__ldcs(&p0[idx]), __ldcs(&p1[idx]))) * enc;
            }
            sc[sy][sx] = v;
        }
    }
    __syncthreads();

#pragma unroll
    for (int k = 0; k < 3; k++) {
        int i = tid + k * 256;
        int sy = i >> 6, sx = i & 63;
        float a = 0.0f;
#pragma unroll
        for (int d = 0; d < 5; d++) a += GX[d] * sc[sy][sx + d];
        ht[sy][sx] = a;
    }
    __syncthreads();

    int cnt = 0;
#pragma unroll
    for (int k = 0; k < 2; k++) {
        int px = tid + k * 256;
        int ty = px >> 6, tx = px & 63;
        float acc = 0.0f;
#pragma unroll
        for (int d = 0; d < 5; d++) acc += GY[d] * ht[ty + d][tx];
        float m = (acc > 0.01f || n % Lq == 0) ? 1.0f : 0.0f;   // ego always communicates
        g_mask[(size_t)n * HWq + (h0 + ty) * Wq + (w0 + tx)] = m;
        unsigned bal = __ballot_sync(0xffffffffu, m > 0.5f);
        if ((tid & 31) == 0) cnt += __popc(bal);
    }
    if ((tid & 31) == 0) atomicAdd(&s_cnt, cnt);
    __syncthreads();
    if (tid == 0) g_blkcnt[flat] = s_cnt;
    __syncthreads();
    cudaTriggerProgrammaticLaunchCompletion();
}

// ============ kernel 2: attention + pooling, f32x2 + streaming loads (64 px/block) ============
// 8 warps; warp w owns channels [8w,8w+8); lane owns a pixel pair; x via __ldcs (evict-first
// keeps out resident in L2 for the scale pass).
__global__ void __launch_bounds__(256, 2) fuse_kernel(
        const float* __restrict__ x,
        const float* __restrict__ inv_delay,
        const float* __restrict__ ew_w,
        const float* __restrict__ ew_b,
        float* __restrict__ out) {
    __shared__ float2 s_buf[8][8][32];     // dots: [w][l<5][lane]; pooling: [w][c][lane]
    __shared__ float2 s_dot[Lq][32];
    __shared__ float s_enw[Lq];

    int b    = blockIdx.y;
    int lane = threadIdx.x & 31;
    int wid  = threadIdx.x >> 5;
    int pp   = blockIdx.x * 32 + lane;       // float2 index: pixels {2pp, 2pp+1}
    int slot = blockIdx.x & (NSLOT - 1);

    if (threadIdx.x < Lq)
        s_enw[threadIdx.x] = tanhf(inv_delay[b * Lq + threadIdx.x] * ew_w[0] + ew_b[0]) + 1.0f;

    // front-issue the 40 LDG.64 streaming x loads (no dependence on conf_mask)
    const float2* xb = (const float2*)(x + ((size_t)(b * Lq) * Cq + wid * 8) * HWq) + pp;
    float2 xv[8][Lq];
#pragma unroll
    for (int c = 0; c < 8; c++)
#pragma unroll
        for (int l = 0; l < Lq; l++)
            xv[c][l] = __ldcs(&xb[((size_t)l * Cq + c) * (HWq / 2)]);

    cudaGridDependencySynchronize();         // g_mask / pool-init now visible

    float2 mk[Lq];
#pragma unroll
    for (int l = 0; l < Lq; l++)
        mk[l] = __ldcs(&((const float2*)(g_mask + (size_t)(b * Lq + l) * HWq))[pp]);

    // packed partial dots over this warp's 8 channels
    float2 pd[Lq];
#pragma unroll
    for (int l = 0; l < Lq; l++) pd[l] = make_float2(0.0f, 0.0f);
#pragma unroll
    for (int c = 0; c < 8; c++) {
        float2 e = xv[c][0];
#pragma unroll
        for (int l = 0; l < Lq; l++) pd[l] = fma2(e, xv[c][l], pd[l]);
    }
#pragma unroll
    for (int l = 0; l < Lq; l++) s_buf[wid][l][lane] = pd[l];
    __syncthreads();

    // dot fan-in by 160-thread subset (packed adds)
    if (threadIdx.x < Lq * 32) {
        int l = threadIdx.x >> 5, ln = threadIdx.x & 31;
        float2 t = make_float2(0.0f, 0.0f);
#pragma unroll
        for (int w = 0; w < 8; w++) t = add2(t, s_buf[w][l][ln]);
        s_dot[l][ln] = t;
    }
    __syncthreads();

    // masked AoI scales (packed)
    float2 s[Lq];
#pragma unroll
    for (int l = 0; l < Lq; l++)
        s[l] = mul2(make_float2(s_enw[l], s_enw[l]), mk[l]);

    // scores (packed) — no max-sub (identity; |scv| << 88)
    float2 scv2[Lq];
    {
        float2 s0c = mul2(s[0], make_float2(0.125f, 0.125f));   // 1/sqrt(64)
#pragma unroll
        for (int l = 0; l < Lq; l++)
            scv2[l] = mul2(mul2(s_dot[l][lane], s0c), s[l]);
    }
    float ex[Lq], ey[Lq], esx = 0.0f, esy = 0.0f;
#pragma unroll
    for (int l = 0; l < Lq; l++) {
        ex[l] = __expf(scv2[l].x); esx += ex[l];
        ey[l] = __expf(scv2[l].y); esy += ey[l];
    }
    float2 inv = make_float2(1.0f / esx, 1.0f / esy);
    float2 coef[Lq];
#pragma unroll
    for (int l = 0; l < Lq; l++)
        coef[l] = mul2(mul2(make_float2(ex[l], ey[l]), inv), s[l]);

    // outputs (packed FMA2) -> gmem; per-channel values -> smem for cooperative pooling
    float2* ob = (float2*)(out + ((size_t)b * Cq + wid * 8) * HWq) + pp;
#pragma unroll
    for (int c = 0; c < 8; c++) {
        float2 f = make_float2(0.0f, 0.0f);
#pragma unroll
        for (int l = 0; l < Lq; l++) f = fma2(coef[l], xv[c][l], f);
        ob[(size_t)c * (HWq / 2)] = f;
        s_buf[wid][c][lane] = f;
    }
    __syncthreads();

    // pooling fan-in: 4 threads per (w,c) pair; each sums 8 lanes, 2-level shuffle combine
    {
        int pair = threadIdx.x >> 2;          // 0..63 = w*8+c
        int sub  = threadIdx.x & 3;
        int w = pair >> 3, c = pair & 7;
        float2 a2 = make_float2(0.0f, 0.0f);
        float m = -INFINITY;
#pragma unroll
        for (int k = 0; k < 8; k++) {
            float2 v = s_buf[w][c][sub * 8 + k];
            a2 = add2(a2, v);
            m = fmaxf(m, fmaxf(v.x, v.y));
        }
        float a = a2.x + a2.y;
        a += __shfl_xor_sync(0xffffffffu, a, 1);
        m = fmaxf(m, __shfl_xor_sync(0xffffffffu, m, 1));
        a += __shfl_xor_sync(0xffffffffu, a, 2);
        m = fmaxf(m, __shfl_xor_sync(0xffffffffu, m, 2));
        if (sub == 0) {
            int cb = b * Cq + w * 8 + c;
            atomicAdd(&g_sum_r[slot][cb], a);         // decontended RED.ADD
            atomicMax(&g_max_r[slot][cb], fenc(m));   // decontended RED.MAX.U32
        }
    }
}

// ============ kernel 3: fold slots + gate MLP + comm_rate (single small block) ============
__global__ void __launch_bounds__(256) reduce_gate_kernel(
        const float* __restrict__ w1,   // (4,64)
        const float* __restrict__ w2,   // (64,4)
        float* __restrict__ out, int out_size) {
    __shared__ float s_avg[Bq * Cq];
    __shared__ float s_mx[Bq * Cq];
    __shared__ int s_red[256];

    int tid = threadIdx.x;

    if (tid < Bq * Cq) {
        float a = 0.0f;
#pragma unroll 8
        for (int s = 0; s < NSLOT; s++) a += g_sum_r[s][tid];
        s_avg[tid] = a * (1.0f / HWq);
    } else {
        int c = tid - Bq * Cq;
        unsigned int e = 0u;
#pragma unroll 8
        for (int s = 0; s < NSLOT; s++) e = max(e, g_max_r[s][c]);
        s_mx[c] = fdec(e);
    }

    int t = 0;
    for (int i = tid; i < MASK_BLOCKS; i += 256) t += g_blkcnt[i];
    s_red[tid] = t;
    __syncthreads();

    if (tid < Bq * Cq) {
        int b = tid >> 6, c = tid & 63;
        float og = 0.0f;
#pragma unroll
        for (int j = 0; j < 4; j++) {
            float sa = 0.0f, sm = 0.0f;
            for (int cc = 0; cc < Cq; cc++) {
                float w = w1[j * Cq + cc];
                sa += s_avg[b * Cq + cc] * w;
                sm += s_mx[b * Cq + cc] * w;
            }
            og += (fmaxf(sa, 0.0f) + fmaxf(sm, 0.0f)) * w2[c * 4 + j];
        }
        g_gate[tid] = 1.0f / (1.0f + expf(-og));
    }
    __syncthreads();                       // gate stores complete
    cudaTriggerProgrammaticLaunchCompletion();

    for (int st = 128; st > 0; st >>= 1) {
        __syncthreads();
        if (tid < st) s_red[tid] += s_red[tid + st];
    }
    if (tid == 0 && out_size > OUTQ)
        out[OUTQ] = (float)s_red[0] / (float)NHWq;     // scale never touches out[OUTQ]
}

// ============ kernel 4: streaming gate apply (PDL early load; reads should hit L2) ============
__global__ void __launch_bounds__(256) scale_kernel(float* __restrict__ out) {
    int cg = blockIdx.x >> 5;             // 1024 floats per block; 32 blocks per channel
    float4* o4 = (float4*)out + (size_t)blockIdx.x * 256 + threadIdx.x;
    float4 v = *o4;                        // independent of reduce_gate
    cudaGridDependencySynchronize();       // g_gate now visible
    float g = g_gate[cg];
    v.x *= g; v.y *= g; v.z *= g; v.w *= g;
    *o4 = v;
}

// ---------------- launch ----------------
extern "C" void kernel_launch(void* const* d_in, const int* in_sizes, int n_in,
                              void* d_out, int out_size) {
    const float* x         = (const float*)d_in[0];
    const float* psm       = (const float*)d_in[1];
    const float* inv_delay = (const float*)d_in[2];
    const float* ew_w      = (const float*)d_in[3];
    const float* ew_b      = (const float*)d_in[4];
    const float* ewc_w     = (const float*)d_in[5];
    const float* ewc_b     = (const float*)d_in[6];
    const float* sta_w1    = (const float*)d_in[7];
    const float* sta_w2    = (const float*)d_in[8];
    float* out = (float*)d_out;

    dim3 gm(MGX, MGY, Nq);
    conf_mask_kernel<<<gm, 256>>>(psm, inv_delay, ewc_w, ewc_b);

    cudaLaunchAttribute pdl[1];
    pdl[0].id = cudaLaunchAttributeProgrammaticStreamSerialization;
    pdl[0].val.programmaticStreamSerializationAllowed = 1;

    {
        cudaLaunchConfig_t cfg = {};
        cfg.gridDim  = dim3(HWq / 64, Bq);
        cfg.blockDim = dim3(256);
        cfg.attrs = pdl; cfg.numAttrs = 1;
        cudaLaunchKernelEx(&cfg, fuse_kernel, x, inv_delay, ew_w, ew_b, out);
    }

    reduce_gate_kernel<<<1, 256>>>(sta_w1, sta_w2, out, out_size);

    {
        cudaLaunchConfig_t cfg = {};
        cfg.gridDim  = dim3(OUTQ / 1024);
        cfg.blockDim = dim3(256);
        cfg.attrs = pdl; cfg.numAttrs = 1;
        cudaLaunchKernelEx(&cfg, scale_kernel, out);
    }
}